// round 3
// baseline (speedup 1.0000x reference)
#include <cuda_runtime.h>

#define NN 100000
#define EE 1600000

// Static device scratch (allocation-free per harness rules)
__device__ float g_rs[NN];    // ns[n] * r_k[n]  (value gathered in scatter pass)
__device__ float g_acc[NN];   // edge-scatter accumulator
__device__ float g_ns[NN];    // out_deg^-1/2 (src norm); holds raw out-degree first
__device__ float g_nd[NN];    // in_deg^-1/2  (dst norm); holds raw in-degree first
__device__ int   g_src[EE];   // int32 decoded edge indices
__device__ int   g_dst[EE];
__device__ float g_scal[8];   // s0..s5, w
__device__ int   g_is64;      // 1 if edge indices are int64, 0 if int32

// ---------------------------------------------------------------------------
// Probe index dtype. Reads first 256 elements as int64 (2 KB — safe for both
// int32 (6.4 MB) and int64 (12.8 MB) buffers). True int64 indices are all in
// [0, NN); aliased int32 pairs are ≥ NN with overwhelming probability.
// ---------------------------------------------------------------------------
__global__ void k_probe(const unsigned long long* __restrict__ src) {
    if (threadIdx.x == 0) {
        int ok = 1;
        for (int i = 0; i < 256; i++)
            if (src[i] >= (unsigned long long)NN) { ok = 0; break; }
        g_is64 = ok;
    }
}

// ---------------------------------------------------------------------------
// Collapse the linear channel path: suffix vectors u_l = W_l @ u_{l+1},
// w = W0@...@W5 (scalar), s_l = b_l . u_{l+1}.
// ---------------------------------------------------------------------------
__global__ void k_scalars(const float* __restrict__ W0, const float* __restrict__ b0,
                          const float* __restrict__ W1, const float* __restrict__ b1,
                          const float* __restrict__ W2, const float* __restrict__ b2,
                          const float* __restrict__ W3, const float* __restrict__ b3,
                          const float* __restrict__ W4, const float* __restrict__ b4,
                          const float* __restrict__ W5, const float* __restrict__ b5) {
    __shared__ float u5[32], u4[64], u3[128], u2[64], u1[32];
    int t = threadIdx.x;

    if (t < 32) u5[t] = W5[t];                       // W5: 32x1
    __syncthreads();
    if (t < 64) {                                    // W4: 64x32
        float s = 0.f;
        for (int j = 0; j < 32; j++) s += W4[t * 32 + j] * u5[j];
        u4[t] = s;
    }
    __syncthreads();
    if (t < 128) {                                   // W3: 128x64
        float s = 0.f;
        for (int j = 0; j < 64; j++) s += W3[t * 64 + j] * u4[j];
        u3[t] = s;
    }
    __syncthreads();
    if (t < 64) {                                    // W2: 64x128
        float s = 0.f;
        for (int j = 0; j < 128; j++) s += W2[t * 128 + j] * u3[j];
        u2[t] = s;
    }
    __syncthreads();
    if (t < 32) {                                    // W1: 32x64
        float s = 0.f;
        for (int j = 0; j < 64; j++) s += W1[t * 64 + j] * u2[j];
        u1[t] = s;
    }
    __syncthreads();
    if (t == 0) {
        float w = 0.f, s0 = 0.f;
        for (int j = 0; j < 32; j++)  { w += W0[j] * u1[j]; s0 += b0[j] * u1[j]; }
        float s1 = 0.f; for (int j = 0; j < 64;  j++) s1 += b1[j] * u2[j];
        float s2 = 0.f; for (int j = 0; j < 128; j++) s2 += b2[j] * u3[j];
        float s3 = 0.f; for (int j = 0; j < 64;  j++) s3 += b3[j] * u4[j];
        float s4 = 0.f; for (int j = 0; j < 32;  j++) s4 += b4[j] * u5[j];
        g_scal[0] = s0; g_scal[1] = s1; g_scal[2] = s2;
        g_scal[3] = s3; g_scal[4] = s4; g_scal[5] = b5[0];
        g_scal[6] = w;
    }
}

__global__ void k_zero() {
    int n = blockIdx.x * blockDim.x + threadIdx.x;
    if (n < NN) { g_ns[n] = 0.f; g_nd[n] = 0.f; g_acc[n] = 0.f; }
}

// Decode indices (int32 or int64 per probe flag), clamp, accumulate degrees
// (float atomics are exact for counts < 2^24).
__global__ void k_edges(const void* __restrict__ srcv,
                        const void* __restrict__ dstv) {
    int e = blockIdx.x * blockDim.x + threadIdx.x;
    if (e < EE) {
        long long sl, dl;
        if (g_is64) {
            sl = ((const long long*)srcv)[e];
            dl = ((const long long*)dstv)[e];
        } else {
            sl = ((const int*)srcv)[e];
            dl = ((const int*)dstv)[e];
        }
        int s = (sl < 0) ? 0 : (sl >= NN ? NN - 1 : (int)sl);
        int d = (dl < 0) ? 0 : (dl >= NN ? NN - 1 : (int)dl);
        g_src[e] = s;
        g_dst[e] = d;
        atomicAdd(&g_ns[s], 1.f);
        atomicAdd(&g_nd[d], 1.f);
    }
}

// Finalize norms; r0 = w * x; stage rs = ns * r0.
__global__ void k_init(const float* __restrict__ x) {
    int n = blockIdx.x * blockDim.x + threadIdx.x;
    if (n < NN) {
        float ns = rsqrtf(fmaxf(g_ns[n], 1.f));
        float nd = rsqrtf(fmaxf(g_nd[n], 1.f));
        g_ns[n] = ns;
        g_nd[n] = nd;
        g_rs[n] = ns * g_scal[6] * x[n];
    }
}

// One propagation hop: acc[dst] += rs[src]. 4 edges per thread for MLP.
__global__ void k_scatter() {
    int i = blockIdx.x * blockDim.x + threadIdx.x;
    int base = i * 4;
    if (base + 3 < EE) {
        int4 s = *reinterpret_cast<const int4*>(g_src + base);
        int4 d = *reinterpret_cast<const int4*>(g_dst + base);
        float v0 = __ldg(&g_rs[s.x]);
        float v1 = __ldg(&g_rs[s.y]);
        float v2 = __ldg(&g_rs[s.z]);
        float v3 = __ldg(&g_rs[s.w]);
        atomicAdd(&g_acc[d.x], v0);
        atomicAdd(&g_acc[d.y], v1);
        atomicAdd(&g_acc[d.z], v2);
        atomicAdd(&g_acc[d.w], v3);
    } else if (base < EE) {
        for (int e = base; e < EE; e++)
            atomicAdd(&g_acc[g_dst[e]], __ldg(&g_rs[g_src[e]]));
    }
}

// r_{k+1} = nd*acc + s_k; stage rs = ns * r_{k+1}; re-zero acc for next hop.
__global__ void k_post(int k) {
    int n = blockIdx.x * blockDim.x + threadIdx.x;
    if (n < NN) {
        float v = g_nd[n] * g_acc[n] + g_scal[k];
        g_rs[n] = g_ns[n] * v;
        g_acc[n] = 0.f;
    }
}

// Final hop epilogue: out = |nd*acc + s5|
__global__ void k_final(float* __restrict__ out) {
    int n = blockIdx.x * blockDim.x + threadIdx.x;
    if (n < NN) {
        float v = g_nd[n] * g_acc[n] + g_scal[5];
        out[n] = fabsf(v);
    }
}

extern "C" void kernel_launch(void* const* d_in, const int* in_sizes, int n_in,
                              void* d_out, int out_size) {
    // --- Layout detection via in_sizes ----------------------------------
    // Layout A (dict insertion order): x(100000), src(1.6M), dst(1.6M),
    //                                  W0,b0, W1,b1, W2,b2, W3,b3, W4,b4, W5,b5
    // Layout B (sorted keys):          W0..W5, b0..b5, dst(1.6M), src(1.6M), x(100000)
    const float *x, *W0, *b0, *W1, *b1, *W2, *b2, *W3, *b3, *W4, *b4, *W5, *b5;
    const void *src, *dst;

    if (in_sizes[0] == NN) {
        // Layout A
        x   = (const float*)d_in[0];
        src = d_in[1];
        dst = d_in[2];
        W0 = (const float*)d_in[3];  b0 = (const float*)d_in[4];
        W1 = (const float*)d_in[5];  b1 = (const float*)d_in[6];
        W2 = (const float*)d_in[7];  b2 = (const float*)d_in[8];
        W3 = (const float*)d_in[9];  b3 = (const float*)d_in[10];
        W4 = (const float*)d_in[11]; b4 = (const float*)d_in[12];
        W5 = (const float*)d_in[13]; b5 = (const float*)d_in[14];
    } else {
        // Layout B (alphabetical)
        W0 = (const float*)d_in[0];  W1 = (const float*)d_in[1];
        W2 = (const float*)d_in[2];  W3 = (const float*)d_in[3];
        W4 = (const float*)d_in[4];  W5 = (const float*)d_in[5];
        b0 = (const float*)d_in[6];  b1 = (const float*)d_in[7];
        b2 = (const float*)d_in[8];  b3 = (const float*)d_in[9];
        b4 = (const float*)d_in[10]; b5 = (const float*)d_in[11];
        dst = d_in[12];
        src = d_in[13];
        x   = (const float*)d_in[14];
    }
    float* out = (float*)d_out;

    const int TB = 256;
    const int GN = (NN + TB - 1) / TB;
    const int GE = (EE + TB - 1) / TB;
    const int GS = (EE / 4 + TB - 1) / TB;

    k_probe<<<1, 32>>>((const unsigned long long*)src);
    k_scalars<<<1, 128>>>(W0, b0, W1, b1, W2, b2, W3, b3, W4, b4, W5, b5);
    k_zero<<<GN, TB>>>();
    k_edges<<<GE, TB>>>(src, dst);
    k_init<<<GN, TB>>>(x);

    for (int k = 0; k < 5; k++) {
        k_scatter<<<GS, TB>>>();
        k_post<<<GN, TB>>>(k);
    }
    k_scatter<<<GS, TB>>>();
    k_final<<<GN, TB>>>(out);
}